// round 1
// baseline (speedup 1.0000x reference)
#include <cuda_runtime.h>
#include <math.h>

#define NN 100000
#define MPAD 100096          // 64-row padded M for GEMMs (1564 * 64)
#define NE 600000
#define NG 64
#define D 128
#define G3 384

// ---------------- scratch (device globals; no allocation) ----------------
__device__ float g_x0[MPAD * D];
__device__ float g_x1[MPAD * D];
__device__ float g_S[MPAD * G3];
__device__ float g_agg[MPAD * D];
__device__ float g_GI[MPAD * G3];
__device__ float g_GH[MPAD * G3];
__device__ float g_cnt[MPAD * 4];
__device__ float g_Wc[G3 * D];      // [k=384][o=128]: msg_W reshaped (t,i)->k, transposed
__device__ float g_Bih[D * G3];     // [k=128][o=384] = W_ih^T
__device__ float g_Bhh[D * G3];
__device__ int   g_hist[NN];
__device__ int   g_off[NN + 1];
__device__ int   g_curp[NN];
__device__ int   g_tmp[NN];
__device__ int   g_bsum[128];
__device__ int   g_entries[NE];     // src | (type<<20), grouped by dst
__device__ float g_pool[NG * D];
__device__ float g_pcnt[NG];

// ---------------- preprocessing ----------------
__global__ void k_prep(const float* __restrict__ msgW,
                       const float* __restrict__ Wih,
                       const float* __restrict__ Whh) {
    int i = blockIdx.x * 256 + threadIdx.x;
    if (i < G3 * D) {
        int k = i >> 7, o = i & 127;          // Wc[k][o]
        g_Wc[i] = msgW[(k >> 7) * D * D + o * D + (k & 127)];
    }
    if (i < D * G3) {
        int k = i / G3, o = i % G3;           // B[k][o] = W[o][k]
        g_Bih[i] = Wih[o * D + k];
        g_Bhh[i] = Whh[o * D + k];
    }
}

__global__ void k_init(const int* __restrict__ xt, const int* __restrict__ xk,
                       const float* __restrict__ xs,
                       const float* __restrict__ temb,
                       const float* __restrict__ kemb) {
    int idx = blockIdx.x * 256 + threadIdx.x;
    if (idx >= NN * D) return;
    int n = idx >> 7, d = idx & 127;
    float v;
    if (d < 32)       v = temb[xt[n] * 32 + d];
    else if (d < 64)  v = kemb[xk[n] * 32 + (d - 32)];
    else              v = xs[n * 64 + (d - 64)];
    g_x0[idx] = v;
}

__global__ void k_zero_hist() {
    int i = blockIdx.x * 256 + threadIdx.x;
    if (i < NN) g_hist[i] = 0;
}

__global__ void k_hist(const int* __restrict__ dst, int E) {
    int e = blockIdx.x * 256 + threadIdx.x;
    if (e < E) atomicAdd(&g_hist[dst[e]], 1);
}

__global__ void k_scan1() {
    __shared__ int s[1024];
    int i = blockIdx.x * 1024 + threadIdx.x;
    s[threadIdx.x] = (i < NN) ? g_hist[i] : 0;
    __syncthreads();
    for (int off = 1; off < 1024; off <<= 1) {
        int t = 0;
        if (threadIdx.x >= off) t = s[threadIdx.x - off];
        __syncthreads();
        if (threadIdx.x >= off) s[threadIdx.x] += t;
        __syncthreads();
    }
    if (i < NN) g_tmp[i] = s[threadIdx.x];
    if (threadIdx.x == 1023) g_bsum[blockIdx.x] = s[1023];
}

__global__ void k_scan2(int nb) {
    int acc = 0;
    for (int b = 0; b < nb; b++) { acc += g_bsum[b]; g_bsum[b] = acc; }
}

__global__ void k_scan3() {
    int i = blockIdx.x * 1024 + threadIdx.x;
    if (i < NN) {
        int add = blockIdx.x ? g_bsum[blockIdx.x - 1] : 0;
        g_off[i + 1] = g_tmp[i] + add;
    }
    if (i == 0) g_off[0] = 0;
}

__global__ void k_copycur() {
    int i = blockIdx.x * 256 + threadIdx.x;
    if (i < NN) g_curp[i] = g_off[i];
}

__global__ void k_scatter(const int* __restrict__ src, const int* __restrict__ dst,
                          const int* __restrict__ et, int E) {
    int e = blockIdx.x * 256 + threadIdx.x;
    if (e >= E) return;
    int dd = dst[e];
    int pos = atomicAdd(&g_curp[dd], 1);
    g_entries[pos] = src[e] | (et[e] << 20);
}

// ---------------- per-iteration kernels ----------------
__device__ __forceinline__ void f4add(float4& a, const float4& b) {
    a.x += b.x; a.y += b.y; a.z += b.z; a.w += b.w;
}

// one warp per node: S[n, t*128 + :] = sum of x[src] over incoming edges of type t
__global__ void k_gather(const float* __restrict__ x) {
    int n = blockIdx.x * 8 + (threadIdx.x >> 5);
    if (n >= NN) return;
    int lane = threadIdx.x & 31;
    float4 a0 = make_float4(0.f, 0.f, 0.f, 0.f), a1 = a0, a2 = a0;
    int c0 = 0, c1 = 0, c2 = 0;
    int beg = g_off[n], end = g_off[n + 1];
    for (int j = beg; j < end; ++j) {
        int e = g_entries[j];
        int s = e & 0xFFFFF, t = e >> 20;
        float4 v = ((const float4*)(x + (size_t)s * D))[lane];
        if (t == 0)      { f4add(a0, v); c0++; }
        else if (t == 1) { f4add(a1, v); c1++; }
        else             { f4add(a2, v); c2++; }
    }
    float4* Sp = (float4*)(g_S + (size_t)n * G3);
    Sp[lane] = a0; Sp[32 + lane] = a1; Sp[64 + lane] = a2;
    if (lane == 0) {
        g_cnt[n * 4 + 0] = (float)c0;
        g_cnt[n * 4 + 1] = (float)c1;
        g_cnt[n * 4 + 2] = (float)c2;
    }
}

// C[M,N] = A[M,K] @ B[K,N] + bias.  MODE 0: bias = sum_t cnt[m,t]*bias[t*128+o]
// MODE 1: bias = bias[o].  BM=64, BN=128, BK=16, 128 threads, 8x8 thread tiles.
template <int K, int N, int MODE>
__global__ void __launch_bounds__(128)
k_sgemm(const float* __restrict__ A, const float* __restrict__ B,
        const float* __restrict__ bias, const float* __restrict__ cnt,
        float* __restrict__ C) {
    const int BM = 64, BK = 16;
    __shared__ float As[BK][BM];
    __shared__ float Bs[BK][128];
    int tid = threadIdx.x;
    int bm = blockIdx.x * BM;
    int bn = blockIdx.y * 128;
    int tm = (tid >> 4) * 8;
    int tn = (tid & 15) * 8;
    int a_row = tid >> 2;
    int a_c4  = (tid & 3) * 4;
    int b_row = tid >> 5;
    int b_c4  = (tid & 31) * 4;
    float acc[8][8];
#pragma unroll
    for (int i = 0; i < 8; i++)
#pragma unroll
        for (int j = 0; j < 8; j++) acc[i][j] = 0.f;

    for (int k0 = 0; k0 < K; k0 += BK) {
#pragma unroll
        for (int r = 0; r < 2; r++) {
            int row = a_row + r * 32;
            float4 v = *(const float4*)(A + (size_t)(bm + row) * K + k0 + a_c4);
            As[a_c4 + 0][row] = v.x; As[a_c4 + 1][row] = v.y;
            As[a_c4 + 2][row] = v.z; As[a_c4 + 3][row] = v.w;
        }
#pragma unroll
        for (int r = 0; r < 4; r++) {
            int row = b_row + r * 4;
            *(float4*)&Bs[row][b_c4] =
                *(const float4*)(B + (size_t)(k0 + row) * N + bn + b_c4);
        }
        __syncthreads();
#pragma unroll
        for (int kk = 0; kk < BK; kk++) {
            float a[8], b[8];
#pragma unroll
            for (int i = 0; i < 8; i++) a[i] = As[kk][tm + i];
#pragma unroll
            for (int j = 0; j < 8; j++) b[j] = Bs[kk][tn + j];
#pragma unroll
            for (int i = 0; i < 8; i++)
#pragma unroll
                for (int j = 0; j < 8; j++) acc[i][j] += a[i] * b[j];
        }
        __syncthreads();
    }

#pragma unroll
    for (int i = 0; i < 8; i++) {
        int row = bm + tm + i;
        float c0 = 0.f, c1 = 0.f, c2 = 0.f;
        if (MODE == 0) { c0 = cnt[row * 4]; c1 = cnt[row * 4 + 1]; c2 = cnt[row * 4 + 2]; }
#pragma unroll
        for (int j = 0; j < 8; j += 4) {
            int col = bn + tn + j;
            float4 v;
            v.x = acc[i][j]; v.y = acc[i][j + 1]; v.z = acc[i][j + 2]; v.w = acc[i][j + 3];
            if (MODE == 0) {
                v.x += c0 * bias[col + 0] + c1 * bias[128 + col + 0] + c2 * bias[256 + col + 0];
                v.y += c0 * bias[col + 1] + c1 * bias[128 + col + 1] + c2 * bias[256 + col + 1];
                v.z += c0 * bias[col + 2] + c1 * bias[128 + col + 2] + c2 * bias[256 + col + 2];
                v.w += c0 * bias[col + 3] + c1 * bias[128 + col + 3] + c2 * bias[256 + col + 3];
            } else {
                v.x += bias[col]; v.y += bias[col + 1]; v.z += bias[col + 2]; v.w += bias[col + 3];
            }
            *(float4*)(C + (size_t)row * N + col) = v;
        }
    }
}

__global__ void k_gru(const float* __restrict__ x, float* __restrict__ xn) {
    int idx = blockIdx.x * 256 + threadIdx.x;
    if (idx >= NN * D) return;
    int n = idx >> 7, d = idx & 127;
    size_t b3 = (size_t)n * G3;
    float ir = g_GI[b3 + d],        hr = g_GH[b3 + d];
    float iz = g_GI[b3 + 128 + d],  hz = g_GH[b3 + 128 + d];
    float in_ = g_GI[b3 + 256 + d], hn = g_GH[b3 + 256 + d];
    float r = 1.f / (1.f + expf(-(ir + hr)));
    float z = 1.f / (1.f + expf(-(iz + hz)));
    float nn = tanhf(in_ + r * hn);
    float h = x[idx];
    xn[idx] = (1.f - z) * nn + z * h;
}

// ---------------- readout ----------------
__global__ void k_zero_pool() {
    int i = blockIdx.x * 256 + threadIdx.x;
    if (i < NG * D) g_pool[i] = 0.f;
    if (i < NG) g_pcnt[i] = 0.f;
}

__global__ void k_pool(const float* __restrict__ x, const int* __restrict__ batch) {
    int idx = blockIdx.x * 256 + threadIdx.x;
    if (idx >= NN * D) return;
    int n = idx >> 7, d = idx & 127;
    int g = batch[n];
    atomicAdd(&g_pool[g * D + d], x[idx]);
    if (d == 0) atomicAdd(&g_pcnt[g], 1.f);
}

__global__ void k_mlp(const float* __restrict__ W1, const float* __restrict__ b1,
                      const float* __restrict__ W2, const float* __restrict__ b2,
                      float* __restrict__ out) {
    int g = blockIdx.x;
    int d = threadIdx.x;  // 128 threads
    __shared__ float ps[128];
    __shared__ float red[4];
    float c = g_pcnt[g]; if (c < 1.f) c = 1.f;
    ps[d] = g_pool[g * D + d] / c;
    __syncthreads();
    float acc = b1[d];
#pragma unroll
    for (int k = 0; k < 128; k++) acc += ps[k] * W1[d * 128 + k];
    float h = acc > 0.f ? acc : 0.f;
    float v = h * W2[d];
#pragma unroll
    for (int off = 16; off; off >>= 1) v += __shfl_down_sync(0xffffffff, v, off);
    if ((d & 31) == 0) red[d >> 5] = v;
    __syncthreads();
    if (d == 0) out[g] = red[0] + red[1] + red[2] + red[3] + b2[0];
}

// ---------------- launch ----------------
extern "C" void kernel_launch(void* const* d_in, const int* in_sizes, int n_in,
                              void* d_out, int out_size) {
    const int*   x_type   = (const int*)d_in[0];
    const int*   x_tok    = (const int*)d_in[1];
    const float* x_small  = (const float*)d_in[2];
    const int*   ei       = (const int*)d_in[3];
    const int*   etype    = (const int*)d_in[4];
    const int*   batch    = (const int*)d_in[5];
    const float* msg_W    = (const float*)d_in[8];
    const float* msg_b    = (const float*)d_in[9];
    const float* W_ih     = (const float*)d_in[10];
    const float* W_hh     = (const float*)d_in[11];
    const float* b_ih     = (const float*)d_in[12];
    const float* b_hh     = (const float*)d_in[13];
    const float* pW1      = (const float*)d_in[14];
    const float* pb1      = (const float*)d_in[15];
    const float* pW2      = (const float*)d_in[16];
    const float* pb2      = (const float*)d_in[17];
    const float* type_emb = (const float*)d_in[6];
    const float* tok_emb  = (const float*)d_in[7];

    const int E = NE;
    const int* src = ei;
    const int* dst = ei + E;

    float *pS, *pAgg, *pGI, *pGH, *pX0, *pX1, *pWc, *pBih, *pBhh, *pCnt;
    cudaGetSymbolAddress((void**)&pS,   g_S);
    cudaGetSymbolAddress((void**)&pAgg, g_agg);
    cudaGetSymbolAddress((void**)&pGI,  g_GI);
    cudaGetSymbolAddress((void**)&pGH,  g_GH);
    cudaGetSymbolAddress((void**)&pX0,  g_x0);
    cudaGetSymbolAddress((void**)&pX1,  g_x1);
    cudaGetSymbolAddress((void**)&pWc,  g_Wc);
    cudaGetSymbolAddress((void**)&pBih, g_Bih);
    cudaGetSymbolAddress((void**)&pBhh, g_Bhh);
    cudaGetSymbolAddress((void**)&pCnt, g_cnt);

    // preprocessing (once per launch; edges/weights static within a launch)
    k_prep<<<(49152 + 255) / 256, 256>>>(msg_W, W_ih, W_hh);
    k_init<<<(NN * D + 255) / 256, 256>>>(x_type, x_tok, x_small, type_emb, tok_emb);
    k_zero_hist<<<(NN + 255) / 256, 256>>>();
    k_hist<<<(E + 255) / 256, 256>>>(dst, E);
    k_scan1<<<98, 1024>>>();
    k_scan2<<<1, 1>>>(98);
    k_scan3<<<98, 1024>>>();
    k_copycur<<<(NN + 255) / 256, 256>>>();
    k_scatter<<<(E + 255) / 256, 256>>>(src, dst, etype, E);

    float* cur = pX0;
    float* nxt = pX1;
    dim3 gA(MPAD / 64, 1);
    dim3 gG(MPAD / 64, 3);
    for (int it = 0; it < 8; it++) {
        k_gather<<<(NN + 7) / 8, 256>>>(cur);
        k_sgemm<384, 128, 0><<<gA, 128>>>(pS, pWc, msg_b, pCnt, pAgg);
        k_sgemm<128, 384, 1><<<gG, 128>>>(pAgg, pBih, b_ih, nullptr, pGI);
        k_sgemm<128, 384, 1><<<gG, 128>>>(cur, pBhh, b_hh, nullptr, pGH);
        k_gru<<<(NN * D + 255) / 256, 256>>>(cur, nxt);
        float* t = cur; cur = nxt; nxt = t;
    }

    k_zero_pool<<<33, 256>>>();
    k_pool<<<(NN * D + 255) / 256, 256>>>(cur, batch);
    k_mlp<<<NG, 128>>>(pW1, pb1, pW2, pb2, (float*)d_out);
}

// round 2
// speedup vs baseline: 1.6415x; 1.6415x over previous
#include <cuda_runtime.h>
#include <math.h>

#define NN 100000
#define MPAD 100096          // 128-row padded M for GEMMs (782 * 128)
#define NE 600000
#define NG 64
#define D 128
#define G3 384

// ---------------- scratch (device globals; no allocation) ----------------
__device__ float g_x0[MPAD * D];
__device__ float g_x1[MPAD * D];
__device__ float g_S[MPAD * G3];
__device__ float g_agg[MPAD * D];
__device__ float g_GI[MPAD * G3];
__device__ float g_GH[MPAD * G3];
__device__ float g_cnt[MPAD * 4];
__device__ float g_Wc[G3 * D];      // [k=384][o=128]: msg_W reshaped (t,i)->k, transposed
__device__ float g_Bih[D * G3];     // [k=128][o=384] = W_ih^T
__device__ float g_Bhh[D * G3];
__device__ int   g_hist[NN];
__device__ int   g_off[NN + 1];
__device__ int   g_curp[NN];
__device__ int   g_tmp[NN];
__device__ int   g_bsum[128];
__device__ int   g_entries[NE];     // src | (type<<20), grouped by dst
__device__ float g_pool[NG * D];
__device__ float g_pcnt[NG];

// ---------------- preprocessing ----------------
__global__ void k_prep(const float* __restrict__ msgW,
                       const float* __restrict__ Wih,
                       const float* __restrict__ Whh) {
    int i = blockIdx.x * 256 + threadIdx.x;
    if (i < G3 * D) {
        int k = i >> 7, o = i & 127;          // Wc[k][o]
        g_Wc[i] = msgW[(k >> 7) * D * D + o * D + (k & 127)];
    }
    if (i < D * G3) {
        int k = i / G3, o = i % G3;           // B[k][o] = W[o][k]
        g_Bih[i] = Wih[o * D + k];
        g_Bhh[i] = Whh[o * D + k];
    }
}

__global__ void k_init(const int* __restrict__ xt, const int* __restrict__ xk,
                       const float* __restrict__ xs,
                       const float* __restrict__ temb,
                       const float* __restrict__ kemb) {
    int idx = blockIdx.x * 256 + threadIdx.x;
    if (idx >= NN * D) return;
    int n = idx >> 7, d = idx & 127;
    float v;
    if (d < 32)       v = temb[xt[n] * 32 + d];
    else if (d < 64)  v = kemb[xk[n] * 32 + (d - 32)];
    else              v = xs[n * 64 + (d - 64)];
    g_x0[idx] = v;
}

__global__ void k_zero_hist() {
    int i = blockIdx.x * 256 + threadIdx.x;
    if (i < NN) g_hist[i] = 0;
}

__global__ void k_hist(const int* __restrict__ dst, int E) {
    int e = blockIdx.x * 256 + threadIdx.x;
    if (e < E) atomicAdd(&g_hist[dst[e]], 1);
}

__global__ void k_scan1() {
    __shared__ int s[1024];
    int i = blockIdx.x * 1024 + threadIdx.x;
    s[threadIdx.x] = (i < NN) ? g_hist[i] : 0;
    __syncthreads();
    for (int off = 1; off < 1024; off <<= 1) {
        int t = 0;
        if (threadIdx.x >= off) t = s[threadIdx.x - off];
        __syncthreads();
        if (threadIdx.x >= off) s[threadIdx.x] += t;
        __syncthreads();
    }
    if (i < NN) g_tmp[i] = s[threadIdx.x];
    if (threadIdx.x == 1023) g_bsum[blockIdx.x] = s[1023];
}

__global__ void k_scan2(int nb) {
    int acc = 0;
    for (int b = 0; b < nb; b++) { acc += g_bsum[b]; g_bsum[b] = acc; }
}

__global__ void k_scan3() {
    int i = blockIdx.x * 1024 + threadIdx.x;
    if (i < NN) {
        int add = blockIdx.x ? g_bsum[blockIdx.x - 1] : 0;
        g_off[i + 1] = g_tmp[i] + add;
    }
    if (i == 0) g_off[0] = 0;
}

__global__ void k_copycur() {
    int i = blockIdx.x * 256 + threadIdx.x;
    if (i < NN) g_curp[i] = g_off[i];
}

__global__ void k_scatter(const int* __restrict__ src, const int* __restrict__ dst,
                          const int* __restrict__ et, int E) {
    int e = blockIdx.x * 256 + threadIdx.x;
    if (e >= E) return;
    int dd = dst[e];
    int pos = atomicAdd(&g_curp[dd], 1);
    g_entries[pos] = src[e] | (et[e] << 20);
}

// ---------------- per-iteration kernels ----------------
__device__ __forceinline__ void f4add(float4& a, const float4& b) {
    a.x += b.x; a.y += b.y; a.z += b.z; a.w += b.w;
}

// one warp per node: S[n, t*128 + :] = sum of x[src] over incoming edges of type t
__global__ void k_gather(const float* __restrict__ x) {
    int n = blockIdx.x * 8 + (threadIdx.x >> 5);
    if (n >= NN) return;
    int lane = threadIdx.x & 31;
    float4 a0 = make_float4(0.f, 0.f, 0.f, 0.f), a1 = a0, a2 = a0;
    int c0 = 0, c1 = 0, c2 = 0;
    int beg = g_off[n], end = g_off[n + 1];
    for (int j = beg; j < end; ++j) {
        int e = g_entries[j];
        int s = e & 0xFFFFF, t = e >> 20;
        float4 v = ((const float4*)(x + (size_t)s * D))[lane];
        if (t == 0)      { f4add(a0, v); c0++; }
        else if (t == 1) { f4add(a1, v); c1++; }
        else             { f4add(a2, v); c2++; }
    }
    float4* Sp = (float4*)(g_S + (size_t)n * G3);
    Sp[lane] = a0; Sp[32 + lane] = a1; Sp[64 + lane] = a2;
    if (lane == 0) {
        g_cnt[n * 4 + 0] = (float)c0;
        g_cnt[n * 4 + 1] = (float)c1;
        g_cnt[n * 4 + 2] = (float)c2;
    }
}

// ---------------- tf32 tensor-core GEMM ----------------
__device__ __forceinline__ float tf32r(float x) {
    unsigned u;
    asm("cvt.rna.tf32.f32 %0, %1;" : "=r"(u) : "f"(x));
    return __uint_as_float(u);
}

__device__ __forceinline__ void mma_tf32(float c[4], const unsigned a[4],
                                         unsigned b0, unsigned b1) {
    asm volatile(
        "mma.sync.aligned.m16n8k8.row.col.f32.tf32.tf32.f32 "
        "{%0,%1,%2,%3}, {%4,%5,%6,%7}, {%8,%9}, {%0,%1,%2,%3};"
        : "+f"(c[0]), "+f"(c[1]), "+f"(c[2]), "+f"(c[3])
        : "r"(a[0]), "r"(a[1]), "r"(a[2]), "r"(a[3]), "r"(b0), "r"(b1));
}

// C[M,N] = A[M,K] @ B[K,N] + bias.
// MODE 0: bias[m,o] = sum_t cnt[m,t]*bias[t*128+o]   (N=128)
// MODE 1: bias[o].
// Block tile 128x128, BK=16, 256 threads (8 warps, 32x64 warp tiles), double-buffered.
template <int K, int N, int MODE>
__global__ void __launch_bounds__(256)
k_mma(const float* __restrict__ A, const float* __restrict__ B,
      const float* __restrict__ bias, const float* __restrict__ cnt,
      float* __restrict__ C) {
    const int BM = 128, BN = 128, BK = 16;
    __shared__ float As[2][BM][BK + 4];   // stride 20: banks (4*gid+tig) unique
    __shared__ float Bs[2][BK][BN + 8];   // stride 136: banks (8*tig+gid) unique

    const int tid  = threadIdx.x;
    const int wid  = tid >> 5, lane = tid & 31;
    const int gid  = lane >> 2, tig = lane & 3;
    const int wm   = (wid >> 1) * 32;
    const int wn   = (wid & 1) * 64;
    const int bm   = blockIdx.x * BM;
    const int bn   = blockIdx.y * BN;

    // staging indices
    const int ar = tid >> 1;            // 0..127
    const int ac = (tid & 1) * 8;       // + i*4, i<2
    const int br = tid >> 4;            // 0..15
    const int bc = (tid & 15) * 4;      // + i*64, i<2

    float acc[2][8][4];
#pragma unroll
    for (int mt = 0; mt < 2; mt++)
#pragma unroll
        for (int nt = 0; nt < 8; nt++)
#pragma unroll
            for (int q = 0; q < 4; q++) acc[mt][nt][q] = 0.f;

    const int NC = K / BK;

    // stage chunk 0
#pragma unroll
    for (int i = 0; i < 2; i++) {
        float4 v = *(const float4*)(A + (size_t)(bm + ar) * K + ac + i * 4);
        float* p = &As[0][ar][ac + i * 4];
        p[0] = tf32r(v.x); p[1] = tf32r(v.y); p[2] = tf32r(v.z); p[3] = tf32r(v.w);
    }
#pragma unroll
    for (int i = 0; i < 2; i++) {
        float4 v = *(const float4*)(B + (size_t)br * N + bn + bc + i * 64);
        float* p = &Bs[0][br][bc + i * 64];
        p[0] = tf32r(v.x); p[1] = tf32r(v.y); p[2] = tf32r(v.z); p[3] = tf32r(v.w);
    }
    __syncthreads();

    for (int c = 0; c < NC; c++) {
        int buf = c & 1;
        if (c + 1 < NC) {
            int k0 = (c + 1) * BK;
#pragma unroll
            for (int i = 0; i < 2; i++) {
                float4 v = *(const float4*)(A + (size_t)(bm + ar) * K + k0 + ac + i * 4);
                float* p = &As[buf ^ 1][ar][ac + i * 4];
                p[0] = tf32r(v.x); p[1] = tf32r(v.y); p[2] = tf32r(v.z); p[3] = tf32r(v.w);
            }
#pragma unroll
            for (int i = 0; i < 2; i++) {
                float4 v = *(const float4*)(B + (size_t)(k0 + br) * N + bn + bc + i * 64);
                float* p = &Bs[buf ^ 1][br][bc + i * 64];
                p[0] = tf32r(v.x); p[1] = tf32r(v.y); p[2] = tf32r(v.z); p[3] = tf32r(v.w);
            }
        }
#pragma unroll
        for (int kk = 0; kk < BK; kk += 8) {
            unsigned a[2][4];
#pragma unroll
            for (int mt = 0; mt < 2; mt++) {
                int m = wm + mt * 16;
                a[mt][0] = __float_as_uint(As[buf][m + gid][kk + tig]);
                a[mt][1] = __float_as_uint(As[buf][m + gid + 8][kk + tig]);
                a[mt][2] = __float_as_uint(As[buf][m + gid][kk + tig + 4]);
                a[mt][3] = __float_as_uint(As[buf][m + gid + 8][kk + tig + 4]);
            }
#pragma unroll
            for (int nt = 0; nt < 8; nt++) {
                unsigned b0 = __float_as_uint(Bs[buf][kk + tig][wn + nt * 8 + gid]);
                unsigned b1 = __float_as_uint(Bs[buf][kk + tig + 4][wn + nt * 8 + gid]);
#pragma unroll
                for (int mt = 0; mt < 2; mt++) mma_tf32(acc[mt][nt], a[mt], b0, b1);
            }
        }
        __syncthreads();
    }

    // epilogue
#pragma unroll
    for (int mt = 0; mt < 2; mt++) {
        int r0 = bm + wm + mt * 16 + gid;
        int r1 = r0 + 8;
        float c00 = 0.f, c01 = 0.f, c02 = 0.f, c10 = 0.f, c11 = 0.f, c12 = 0.f;
        if (MODE == 0) {
            c00 = cnt[r0 * 4]; c01 = cnt[r0 * 4 + 1]; c02 = cnt[r0 * 4 + 2];
            c10 = cnt[r1 * 4]; c11 = cnt[r1 * 4 + 1]; c12 = cnt[r1 * 4 + 2];
        }
#pragma unroll
        for (int nt = 0; nt < 8; nt++) {
            int col = bn + wn + nt * 8 + tig * 2;
            float2 v0, v1;
            if (MODE == 0) {
                float ba = bias[col],       bb = bias[col + 1];
                float bc1 = bias[128 + col], bd = bias[128 + col + 1];
                float be = bias[256 + col], bf = bias[256 + col + 1];
                v0.x = acc[mt][nt][0] + c00 * ba + c01 * bc1 + c02 * be;
                v0.y = acc[mt][nt][1] + c00 * bb + c01 * bd + c02 * bf;
                v1.x = acc[mt][nt][2] + c10 * ba + c11 * bc1 + c12 * be;
                v1.y = acc[mt][nt][3] + c10 * bb + c11 * bd + c12 * bf;
            } else {
                float ba = bias[col], bb = bias[col + 1];
                v0.x = acc[mt][nt][0] + ba;
                v0.y = acc[mt][nt][1] + bb;
                v1.x = acc[mt][nt][2] + ba;
                v1.y = acc[mt][nt][3] + bb;
            }
            *(float2*)(C + (size_t)r0 * N + col) = v0;
            *(float2*)(C + (size_t)r1 * N + col) = v1;
        }
    }
}

__global__ void k_gru(const float* __restrict__ x, float* __restrict__ xn) {
    int idx = blockIdx.x * 256 + threadIdx.x;
    if (idx >= NN * D) return;
    int n = idx >> 7, d = idx & 127;
    size_t b3 = (size_t)n * G3;
    float ir = g_GI[b3 + d],        hr = g_GH[b3 + d];
    float iz = g_GI[b3 + 128 + d],  hz = g_GH[b3 + 128 + d];
    float in_ = g_GI[b3 + 256 + d], hn = g_GH[b3 + 256 + d];
    float r = 1.f / (1.f + expf(-(ir + hr)));
    float z = 1.f / (1.f + expf(-(iz + hz)));
    float nn = tanhf(in_ + r * hn);
    float h = x[idx];
    xn[idx] = (1.f - z) * nn + z * h;
}

// ---------------- readout ----------------
__global__ void k_zero_pool() {
    int i = blockIdx.x * 256 + threadIdx.x;
    if (i < NG * D) g_pool[i] = 0.f;
    if (i < NG) g_pcnt[i] = 0.f;
}

__global__ void k_pool(const float* __restrict__ x, const int* __restrict__ batch) {
    int idx = blockIdx.x * 256 + threadIdx.x;
    if (idx >= NN * D) return;
    int n = idx >> 7, d = idx & 127;
    int g = batch[n];
    atomicAdd(&g_pool[g * D + d], x[idx]);
    if (d == 0) atomicAdd(&g_pcnt[g], 1.f);
}

__global__ void k_mlp(const float* __restrict__ W1, const float* __restrict__ b1,
                      const float* __restrict__ W2, const float* __restrict__ b2,
                      float* __restrict__ out) {
    int g = blockIdx.x;
    int d = threadIdx.x;  // 128 threads
    __shared__ float ps[128];
    __shared__ float red[4];
    float c = g_pcnt[g]; if (c < 1.f) c = 1.f;
    ps[d] = g_pool[g * D + d] / c;
    __syncthreads();
    float acc = b1[d];
#pragma unroll
    for (int k = 0; k < 128; k++) acc += ps[k] * W1[d * 128 + k];
    float h = acc > 0.f ? acc : 0.f;
    float v = h * W2[d];
#pragma unroll
    for (int off = 16; off; off >>= 1) v += __shfl_down_sync(0xffffffff, v, off);
    if ((d & 31) == 0) red[d >> 5] = v;
    __syncthreads();
    if (d == 0) out[g] = red[0] + red[1] + red[2] + red[3] + b2[0];
}

// ---------------- launch ----------------
extern "C" void kernel_launch(void* const* d_in, const int* in_sizes, int n_in,
                              void* d_out, int out_size) {
    const int*   x_type   = (const int*)d_in[0];
    const int*   x_tok    = (const int*)d_in[1];
    const float* x_small  = (const float*)d_in[2];
    const int*   ei       = (const int*)d_in[3];
    const int*   etype    = (const int*)d_in[4];
    const int*   batch    = (const int*)d_in[5];
    const float* type_emb = (const float*)d_in[6];
    const float* tok_emb  = (const float*)d_in[7];
    const float* msg_W    = (const float*)d_in[8];
    const float* msg_b    = (const float*)d_in[9];
    const float* W_ih     = (const float*)d_in[10];
    const float* W_hh     = (const float*)d_in[11];
    const float* b_ih     = (const float*)d_in[12];
    const float* b_hh     = (const float*)d_in[13];
    const float* pW1      = (const float*)d_in[14];
    const float* pb1      = (const float*)d_in[15];
    const float* pW2      = (const float*)d_in[16];
    const float* pb2      = (const float*)d_in[17];

    const int E = NE;
    const int* src = ei;
    const int* dst = ei + E;

    float *pS, *pAgg, *pGI, *pGH, *pX0, *pX1, *pWc, *pBih, *pBhh, *pCnt;
    cudaGetSymbolAddress((void**)&pS,   g_S);
    cudaGetSymbolAddress((void**)&pAgg, g_agg);
    cudaGetSymbolAddress((void**)&pGI,  g_GI);
    cudaGetSymbolAddress((void**)&pGH,  g_GH);
    cudaGetSymbolAddress((void**)&pX0,  g_x0);
    cudaGetSymbolAddress((void**)&pX1,  g_x1);
    cudaGetSymbolAddress((void**)&pWc,  g_Wc);
    cudaGetSymbolAddress((void**)&pBih, g_Bih);
    cudaGetSymbolAddress((void**)&pBhh, g_Bhh);
    cudaGetSymbolAddress((void**)&pCnt, g_cnt);

    // preprocessing (once per launch; edges/weights static within a launch)
    k_prep<<<(49152 + 255) / 256, 256>>>(msg_W, W_ih, W_hh);
    k_init<<<(NN * D + 255) / 256, 256>>>(x_type, x_tok, x_small, type_emb, tok_emb);
    k_zero_hist<<<(NN + 255) / 256, 256>>>();
    k_hist<<<(E + 255) / 256, 256>>>(dst, E);
    k_scan1<<<98, 1024>>>();
    k_scan2<<<1, 1>>>(98);
    k_scan3<<<98, 1024>>>();
    k_copycur<<<(NN + 255) / 256, 256>>>();
    k_scatter<<<(E + 255) / 256, 256>>>(src, dst, etype, E);

    float* cur = pX0;
    float* nxt = pX1;
    dim3 gA(MPAD / 128, 1);
    dim3 gG(MPAD / 128, 3);
    for (int it = 0; it < 8; it++) {
        k_gather<<<(NN + 7) / 8, 256>>>(cur);
        k_mma<384, 128, 0><<<gA, 256>>>(pS, pWc, msg_b, pCnt, pAgg);
        k_mma<128, 384, 1><<<gG, 256>>>(pAgg, pBih, b_ih, nullptr, pGI);
        k_mma<128, 384, 1><<<gG, 256>>>(cur, pBhh, b_hh, nullptr, pGH);
        k_gru<<<(NN * D + 255) / 256, 256>>>(cur, nxt);
        float* t = cur; cur = nxt; nxt = t;
    }

    k_zero_pool<<<33, 256>>>();
    k_pool<<<(NN * D + 255) / 256, 256>>>(cur, batch);
    k_mlp<<<NG, 128>>>(pW1, pb1, pW2, pb2, (float*)d_out);
}